// round 11
// baseline (speedup 1.0000x reference)
#include <cuda_runtime.h>
#include <cstdint>

#define B_  4
#define Qn  1024
#define Kn  1024
#define QS  256
#define KSZ 256
#define Hn  32
#define VD  256
#define TQ  8
#define TK  128

// Device-global scratch (no runtime allocation allowed)
__device__ float g_fq[B_ * Qn * Hn];
__device__ float g_fk[B_ * Kn * Hn];

typedef unsigned long long u64;

// ---------------- helpers ----------------

__device__ __forceinline__ float fast_tanh(float x) {
    float y;
    asm("tanh.approx.f32 %0, %1;" : "=f"(y) : "f"(x));
    return y;
}

__device__ __forceinline__ float warp_sum(float v) {
    #pragma unroll
    for (int o = 16; o > 0; o >>= 1) v += __shfl_xor_sync(0xFFFFFFFFu, v, o);
    return v;
}

__device__ __forceinline__ u64 pack2(float lo, float hi) {
    u64 r;
    asm("mov.b64 %0, {%1, %2};" : "=l"(r) : "f"(lo), "f"(hi));
    return r;
}
__device__ __forceinline__ void unpack2(u64 a, float& lo, float& hi) {
    asm("mov.b64 {%0, %1}, %2;" : "=f"(lo), "=f"(hi) : "l"(a));
}
__device__ __forceinline__ u64 add2(u64 a, u64 b) {
    u64 r;
    asm("add.rn.f32x2 %0, %1, %2;" : "=l"(r) : "l"(a), "l"(b));
    return r;
}
__device__ __forceinline__ void fma2(u64& a, u64 v, u64 p) {
    asm("fma.rn.f32x2 %0, %1, %2, %0;" : "+l"(a) : "l"(v), "l"(p));
}

__device__ __forceinline__ void cp_async16(unsigned int dst_smem, const void* src) {
    asm volatile("cp.async.ca.shared.global [%0], [%1], 16;" :: "r"(dst_smem), "l"(src));
}
__device__ __forceinline__ void cp_async_commit() {
    asm volatile("cp.async.commit_group;");
}
__device__ __forceinline__ void cp_async_wait0() {
    asm volatile("cp.async.wait_group 0;");
}

// ---------------- kernel 1: projections fq = q@Wq+bq, fk = k@Wk+bk ----------------
// Thread owns 8 consecutive rows x 1 h-pair (hp = lane&15, rg = lane>>4).
// Warp covers 16 rows. Per j4: 4 W LDG.64 shared across all 8 rows + 8 x
// LDG.128 (2 coalesced addrs each) = 12 LDG-warp-instrs / 16 rows, 32 fma2.
// CTA = 64 threads (2 warps) = 32 rows; grid = 8192/32 = 256.

__global__ __launch_bounds__(64)
void proj_kernel(const float* __restrict__ queries, const float* __restrict__ keys,
                 const float* __restrict__ Wq, const float* __restrict__ bq,
                 const float* __restrict__ Wk, const float* __restrict__ bk,
                 const int* __restrict__ valid_lens) {
    const int lane = threadIdx.x & 31;
    const int wid  = threadIdx.x >> 5;
    const int hp   = lane & 15;          // h-pair index: h = 2hp, 2hp+1
    const int rg   = lane >> 4;          // row-octet within warp
    const int rowbase = (blockIdx.x * 2 + wid) * 16 + rg * 8;   // 8 consecutive rows

    const float* srcbase; const u64* Wp; const u64* biasp; u64* dstbase;
    int nstore = 8;                      // rows [rowbase, rowbase+nstore) get stored
    if (rowbase < B_ * Qn) {
        srcbase = queries; Wp = (const u64*)Wq; biasp = (const u64*)bq;
        dstbase = (u64*)g_fq;
    } else {
        int r2 = rowbase - B_ * Qn;
        int valid = valid_lens[r2 >> 10];
        int kpos  = r2 & (Kn - 1);       // 8-aligned; octet never crosses a batch
        if (kpos >= valid) return;       // whole octet masked downstream -> skip
        int rem = valid - kpos;
        nstore = rem < 8 ? rem : 8;
        srcbase = keys - (size_t)(B_ * Qn) * KSZ;    // srcbase + row*KSZ is correct
        Wp = (const u64*)Wk; biasp = (const u64*)bk;
        dstbase = (u64*)g_fk - (size_t)(B_ * Qn) * (Hn / 2);
    }

    const float4* s = (const float4*)(srcbase + (size_t)rowbase * QS);
    const int rstride = QS / 4;          // float4 stride between rows

    u64 acc[8];
    #pragma unroll
    for (int i = 0; i < 8; i++) acc[i] = 0ull;

    #pragma unroll 4
    for (int j4 = 0; j4 < QS / 4; j4++) {
        const u64* wrow = Wp + (size_t)(4 * j4) * (Hn / 2) + hp;
        u64 w0 = __ldg(&wrow[0]);
        u64 w1 = __ldg(&wrow[Hn / 2]);
        u64 w2 = __ldg(&wrow[Hn]);
        u64 w3 = __ldg(&wrow[3 * Hn / 2]);
        #pragma unroll
        for (int i = 0; i < 8; i++) {
            float4 x = __ldg(&s[i * rstride + j4]);
            fma2(acc[i], pack2(x.x, x.x), w0);
            fma2(acc[i], pack2(x.y, x.y), w1);
            fma2(acc[i], pack2(x.z, x.z), w2);
            fma2(acc[i], pack2(x.w, x.w), w3);
        }
    }

    u64 bias = __ldg(&biasp[hp]);
    u64* d = dstbase + (size_t)rowbase * (Hn / 2) + hp;
    #pragma unroll
    for (int i = 0; i < 8; i++) {
        if (i < nstore) d[i * (Hn / 2)] = add2(acc[i], bias);
    }
}

// ---------------- attn phase helpers (generic / masked paths) ----------------

__device__ __forceinline__ void phaseA(const float* fkbuf, const float* fq_w,
                                       const float* wv, u64* pdst,
                                       int w, int lane, int kb, int valid,
                                       float& l_run) {
    float sacc[4] = {0.f, 0.f, 0.f, 0.f};
    const float4* fq4 = (const float4*)fq_w;
    const float4* wv4 = (const float4*)wv;
    const float4* fk4 = (const float4*)fkbuf;
    #pragma unroll
    for (int hb = 0; hb < 8; hb++) {
        float4 a = fq4[hb];
        float4 g = wv4[hb];
        #pragma unroll
        for (int i = 0; i < 4; i++) {
            float4 f = fk4[(lane + 32 * i) * 9 + hb];
            sacc[i] = fmaf(g.x, fast_tanh(a.x + f.x), sacc[i]);
            sacc[i] = fmaf(g.y, fast_tanh(a.y + f.y), sacc[i]);
            sacc[i] = fmaf(g.z, fast_tanh(a.z + f.z), sacc[i]);
            sacc[i] = fmaf(g.w, fast_tanh(a.w + f.w), sacc[i]);
        }
    }
    #pragma unroll
    for (int i = 0; i < 4; i++) {
        float p = (kb + lane + 32 * i < valid) ? __expf(sacc[i]) : 0.0f;
        l_run += p;
        pdst[(lane + 32 * i) * 10 + w] = pack2(p, p);
    }
}

__device__ __forceinline__ void phaseB(const u64* psrc, const float* vbatch,
                                       int kb, int valid, int w, int lane,
                                       u64 acc[TQ][2]) {
    const int kloc0 = (w >> 1) * 32;
    const int voff  = (w & 1) * 128;
    const u64* pbase = psrc + kloc0 * 10;
    const float* vb = vbatch + (size_t)(kb + kloc0) * VD + voff;
    int rem = valid - kb - kloc0;
    int kend = rem < 32 ? (rem < 0 ? 0 : rem) : 32;
    #pragma unroll 4
    for (int kk = 0; kk < kend; kk++) {
        ulonglong2 v = __ldg((const ulonglong2*)(vb + (size_t)kk * VD) + lane);
        const ulonglong2* prow2 = (const ulonglong2*)(pbase + kk * 10);
        #pragma unroll
        for (int qp = 0; qp < 4; qp++) {
            ulonglong2 pp = prow2[qp];
            fma2(acc[2 * qp][0],     v.x, pp.x);
            fma2(acc[2 * qp][1],     v.y, pp.x);
            fma2(acc[2 * qp + 1][0], v.x, pp.y);
            fma2(acc[2 * qp + 1][1], v.y, pp.y);
        }
    }
}

// ---------------- kernel 2: fused additive attention ----------------
// grid = (B, Q/TQ), block = 256 (8 warps), 3 CTAs/SM.
// Software-pipelined: region c executes A(c+1) [MUFU-heavy] AND B(c) [LSU/FMA-
// heavy] between the same barriers; common full/full case hand-interleaved.
// No online softmax (|score| <= ||w_v||_1 since |tanh|<=1 -> exp safe in fp32).

__global__ __launch_bounds__(256, 3)
void attn_kernel(const float* __restrict__ values, const int* __restrict__ valid_lens,
                 const float* __restrict__ wvec, float* __restrict__ out) {
    __shared__ float fk_s[2][TK * 36];                   // [k][h], stride 36 floats
    __shared__ __align__(16) u64 pT2[2][TK * 10];        // [k][q] dup pair {p,p}, stride 10 u64
    __shared__ float fq_s[TQ * 32];
    __shared__ float wv_s[32];
    __shared__ float l_s[TQ];

    const int tid  = threadIdx.x;
    const int w    = tid >> 5;
    const int lane = tid & 31;
    const int b    = blockIdx.x;
    const int q0   = blockIdx.y * TQ;
    const int valid = valid_lens[b];

    fq_s[w * 32 + lane] = g_fq[((size_t)(b * Qn + q0 + w)) * Hn + lane];
    if (tid < 32) wv_s[tid] = wvec[tid];

    float l_run = 0.0f;
    u64 acc[TQ][2];
    #pragma unroll
    for (int q = 0; q < TQ; q++) { acc[q][0] = 0ull; acc[q][1] = 0ull; }

    const float* vbatch = values + (size_t)b * Kn * VD;
    const int nchunks = (valid + TK - 1) / TK;
    const int nfull   = valid / TK;

    // ---- Preload fk(0) into buffer 0 ----
    {
        const float4* src = (const float4*)(g_fk + ((size_t)(b * Kn)) * Hn);
        #pragma unroll
        for (int r = 0; r < 4; r++) {
            int idx = tid + 256 * r;
            unsigned int dst = (unsigned int)__cvta_generic_to_shared(
                &((float4*)fk_s[0])[(idx >> 3) * 9 + (idx & 7)]);
            cp_async16(dst, &src[idx]);
        }
        cp_async_commit();
        cp_async_wait0();
    }
    __syncthreads();

    // ---- Prologue: prefetch fk(1), compute A(0) ----
    if (nchunks > 1) {
        const float4* src = (const float4*)(g_fk + ((size_t)(b * Kn + TK)) * Hn);
        #pragma unroll
        for (int r = 0; r < 4; r++) {
            int idx = tid + 256 * r;
            unsigned int dst = (unsigned int)__cvta_generic_to_shared(
                &((float4*)fk_s[1])[(idx >> 3) * 9 + (idx & 7)]);
            cp_async16(dst, &src[idx]);
        }
        cp_async_commit();
    }
    phaseA(fk_s[0], fq_s + w * 32, wv_s, pT2[0], w, lane, 0, valid, l_run);
    if (nchunks > 1) cp_async_wait0();
    __syncthreads();

    // ---- Pipelined regions: region c = A(c+1) + B(c) ----
    for (int c = 0; c < nchunks; c++) {
        const int kb   = c * TK;
        const int bufB = c & 1;
        const int bufA = bufB ^ 1;

        if (c + 2 < nchunks) {     // prefetch fk(c+2) into fk_s[bufB] (fk(c) done)
            const float4* src = (const float4*)(g_fk + ((size_t)(b * Kn + kb + 2 * TK)) * Hn);
            #pragma unroll
            for (int r = 0; r < 4; r++) {
                int idx = tid + 256 * r;
                unsigned int dst = (unsigned int)__cvta_generic_to_shared(
                    &((float4*)fk_s[bufB])[(idx >> 3) * 9 + (idx & 7)]);
                cp_async16(dst, &src[idx]);
            }
            cp_async_commit();
        }

        if (c + 1 < nfull) {
            // ======== FAST PATH: A(c+1) full + B(c) full, hand-interleaved ========
            float sacc0 = 0.f, sacc1 = 0.f, sacc2 = 0.f, sacc3 = 0.f;
            const float4* fq4 = (const float4*)(fq_s + w * 32);
            const float4* wv4 = (const float4*)wv_s;
            const float4* fkA = (const float4*)fk_s[bufA];
            const int kloc0 = (w >> 1) * 32;
            const int voff  = (w & 1) * 128;
            const u64* pbase = pT2[bufB] + kloc0 * 10;
            const float* vb = vbatch + (size_t)(kb + kloc0) * VD + voff;

            #pragma unroll
            for (int s = 0; s < 8; s++) {
                float4 a = fq4[s];
                float4 g = wv4[s];
                float4 f0 = fkA[(lane)       * 9 + s];
                float4 f1 = fkA[(lane + 32)  * 9 + s];
                float4 f2 = fkA[(lane + 64)  * 9 + s];
                float4 f3 = fkA[(lane + 96)  * 9 + s];
                sacc0 = fmaf(g.x, fast_tanh(a.x + f0.x), sacc0);
                sacc0 = fmaf(g.y, fast_tanh(a.y + f0.y), sacc0);
                sacc0 = fmaf(g.z, fast_tanh(a.z + f0.z), sacc0);
                sacc0 = fmaf(g.w, fast_tanh(a.w + f0.w), sacc0);
                sacc1 = fmaf(g.x, fast_tanh(a.x + f1.x), sacc1);
                sacc1 = fmaf(g.y, fast_tanh(a.y + f1.y), sacc1);
                sacc1 = fmaf(g.z, fast_tanh(a.z + f1.z), sacc1);
                sacc1 = fmaf(g.w, fast_tanh(a.w + f1.w), sacc1);
                sacc2 = fmaf(g.x, fast_tanh(a.x + f2.x), sacc2);
                sacc2 = fmaf(g.y, fast_tanh(a.y + f2.y), sacc2);
                sacc2 = fmaf(g.z, fast_tanh(a.z + f2.z), sacc2);
                sacc2 = fmaf(g.w, fast_tanh(a.w + f2.w), sacc2);
                sacc3 = fmaf(g.x, fast_tanh(a.x + f3.x), sacc3);
                sacc3 = fmaf(g.y, fast_tanh(a.y + f3.y), sacc3);
                sacc3 = fmaf(g.z, fast_tanh(a.z + f3.z), sacc3);
                sacc3 = fmaf(g.w, fast_tanh(a.w + f3.w), sacc3);
                #pragma unroll
                for (int t = 0; t < 4; t++) {
                    int kk = 4 * s + t;
                    ulonglong2 v = __ldg((const ulonglong2*)(vb + (size_t)kk * VD) + lane);
                    const ulonglong2* prow2 = (const ulonglong2*)(pbase + kk * 10);
                    #pragma unroll
                    for (int qp = 0; qp < 4; qp++) {
                        ulonglong2 pp = prow2[qp];
                        fma2(acc[2 * qp][0],     v.x, pp.x);
                        fma2(acc[2 * qp][1],     v.y, pp.x);
                        fma2(acc[2 * qp + 1][0], v.x, pp.y);
                        fma2(acc[2 * qp + 1][1], v.y, pp.y);
                    }
                }
            }
            float p0 = __expf(sacc0), p1 = __expf(sacc1);
            float p2 = __expf(sacc2), p3 = __expf(sacc3);
            l_run += (p0 + p1) + (p2 + p3);
            pT2[bufA][(lane)       * 10 + w] = pack2(p0, p0);
            pT2[bufA][(lane + 32)  * 10 + w] = pack2(p1, p1);
            pT2[bufA][(lane + 64)  * 10 + w] = pack2(p2, p2);
            pT2[bufA][(lane + 96)  * 10 + w] = pack2(p3, p3);
        } else {
            // ======== GENERIC PATH (tail chunks) ========
            if (c + 1 < nchunks)
                phaseA(fk_s[bufA], fq_s + w * 32, wv_s, pT2[bufA],
                       w, lane, kb + TK, valid, l_run);
            phaseB(pT2[bufB], vbatch, kb, valid, w, lane, acc);
        }

        if (c + 2 < nchunks) cp_async_wait0();
        __syncthreads();
    }

    // -------- Epilogue: row-sums, then single-barrier cross-warp reduction --------
    float l = warp_sum(l_run);
    if (lane == 0) l_s[w] = l;

    float* bufp = fk_s[0];   // 32KB scratch inside fk_s
    #pragma unroll
    for (int q = 0; q < TQ; q++) {
        float f0, f1, f2, f3;
        unpack2(acc[q][0], f0, f1);
        unpack2(acc[q][1], f2, f3);
        float* d = bufp + (q * 8 + w) * 128 + lane * 4;
        d[0] = f0; d[1] = f1; d[2] = f2; d[3] = f3;
    }
    __syncthreads();

    {
        const int vhalf = tid >> 7;
        const int idx   = tid & 127;
        const size_t obase = ((size_t)(b * Qn + q0)) * VD + tid;
        #pragma unroll
        for (int q = 0; q < TQ; q++) {
            const float* s = bufp + q * 1024 + vhalf * 128 + idx;
            float tot = s[0] + s[256] + s[512] + s[768];
            out[obase + (size_t)q * VD] = tot * (1.0f / l_s[q]);
        }
    }
}

// ---------------- launch ----------------

extern "C" void kernel_launch(void* const* d_in, const int* in_sizes, int n_in,
                              void* d_out, int out_size) {
    const float* keys       = (const float*)d_in[0];
    const float* queries    = (const float*)d_in[1];
    const float* values     = (const float*)d_in[2];
    const int*   valid_lens = (const int*)d_in[3];
    const float* W_q        = (const float*)d_in[4];
    const float* b_q        = (const float*)d_in[5];
    const float* W_k        = (const float*)d_in[6];
    const float* b_k        = (const float*)d_in[7];
    const float* w_v        = (const float*)d_in[8];
    // b_v (d_in[9]) is softmax-invariant and intentionally unused.
    float* out = (float*)d_out;

    int total_rows = B_ * (Qn + Kn);            // 8192
    proj_kernel<<<total_rows / 32, 64>>>(queries, keys, W_q, b_q, W_k, b_k, valid_lens);

    dim3 grid(B_, Qn / TQ);
    attn_kernel<<<grid, 256>>>(values, valid_lens, w_v, out);
}

// round 12
// speedup vs baseline: 1.2448x; 1.2448x over previous
#include <cuda_runtime.h>
#include <cstdint>

#define B_  4
#define Qn  1024
#define Kn  1024
#define QS  256
#define KSZ 256
#define Hn  32
#define VD  256
#define TQ  8
#define TK  128

// Device-global scratch (no runtime allocation allowed)
__device__ float g_fq[B_ * Qn * Hn];
__device__ float g_fk[B_ * Kn * Hn];

typedef unsigned long long u64;

// ---------------- helpers ----------------

__device__ __forceinline__ float fast_tanh(float x) {
    float y;
    asm("tanh.approx.f32 %0, %1;" : "=f"(y) : "f"(x));
    return y;
}

__device__ __forceinline__ float warp_sum(float v) {
    #pragma unroll
    for (int o = 16; o > 0; o >>= 1) v += __shfl_xor_sync(0xFFFFFFFFu, v, o);
    return v;
}

__device__ __forceinline__ u64 pack2(float lo, float hi) {
    u64 r;
    asm("mov.b64 %0, {%1, %2};" : "=l"(r) : "f"(lo), "f"(hi));
    return r;
}
__device__ __forceinline__ void unpack2(u64 a, float& lo, float& hi) {
    asm("mov.b64 {%0, %1}, %2;" : "=f"(lo), "=f"(hi) : "l"(a));
}
__device__ __forceinline__ u64 add2(u64 a, u64 b) {
    u64 r;
    asm("add.rn.f32x2 %0, %1, %2;" : "=l"(r) : "l"(a), "l"(b));
    return r;
}
__device__ __forceinline__ void fma2(u64& a, u64 v, u64 p) {
    asm("fma.rn.f32x2 %0, %1, %2, %0;" : "+l"(a) : "l"(v), "l"(p));
}

__device__ __forceinline__ void cp_async16(unsigned int dst_smem, const void* src) {
    asm volatile("cp.async.ca.shared.global [%0], [%1], 16;" :: "r"(dst_smem), "l"(src));
}
__device__ __forceinline__ void cp_async_commit() {
    asm volatile("cp.async.commit_group;");
}
__device__ __forceinline__ void cp_async_wait0() {
    asm volatile("cp.async.wait_group 0;");
}

// ---------------- kernel 1: projections fq = q@Wq+bq, fk = k@Wk+bk ----------------
// CTA = 128 threads (4 warps) covers 16 rows. Warp w handles the j-quarter
// j4 in [16w, 16w+16). Thread: hp = lane&15 (h-pair), rg = lane>>4 (row octet),
// 8 rows/thread. Per j4 per warp: 4 W LDG.64 (shared by all 8 rows) + 8 x
// LDG.128 -> same LDG/row as the amortized version but 2048 warps (~14/SM)
// for latency hiding. Partials reduced through 8KB smem.

__global__ __launch_bounds__(128)
void proj_kernel(const float* __restrict__ queries, const float* __restrict__ keys,
                 const float* __restrict__ Wq, const float* __restrict__ bq,
                 const float* __restrict__ Wk, const float* __restrict__ bk,
                 const int* __restrict__ valid_lens) {
    __shared__ u64 part[4 * 2 * 8 * 16];    // [warp][rg][rowinoctet][hp] = 8KB

    const int tid  = threadIdx.x;
    const int w    = tid >> 5;
    const int lane = tid & 31;
    const int hp   = lane & 15;
    const int rg   = lane >> 4;
    const int rowbase_cta = blockIdx.x * 16;
    const int rowbase = rowbase_cta + rg * 8;

    const bool isQ = rowbase_cta < B_ * Qn;
    const float* srcbase; const u64* Wp; const u64* biasp; u64* dstbase;
    int valid = 0;
    if (isQ) {
        srcbase = queries; Wp = (const u64*)Wq; biasp = (const u64*)bq;
        dstbase = (u64*)g_fq;
    } else {
        int r2 = rowbase_cta - B_ * Qn;
        valid = valid_lens[r2 >> 10];
        // 16-row block is batch-aligned; if its first k-pos is masked, all are.
        if ((r2 & (Kn - 1)) >= valid) return;     // uniform across CTA
        srcbase = keys - (size_t)(B_ * Qn) * KSZ;  // srcbase + row*KSZ is correct
        Wp = (const u64*)Wk; biasp = (const u64*)bk;
        dstbase = (u64*)g_fk - (size_t)(B_ * Qn) * (Hn / 2);
    }

    const float4* s = (const float4*)(srcbase + (size_t)rowbase * QS);
    const int rstride = QS / 4;

    u64 acc[8];
    #pragma unroll
    for (int i = 0; i < 8; i++) acc[i] = 0ull;

    const int j40 = w * 16;
    #pragma unroll 4
    for (int jj = 0; jj < 16; jj++) {
        const int j4 = j40 + jj;
        const u64* wrow = Wp + (size_t)(4 * j4) * (Hn / 2) + hp;
        u64 w0 = __ldg(&wrow[0]);
        u64 w1 = __ldg(&wrow[Hn / 2]);
        u64 w2 = __ldg(&wrow[Hn]);
        u64 w3 = __ldg(&wrow[3 * Hn / 2]);
        #pragma unroll
        for (int i = 0; i < 8; i++) {
            float4 x = __ldg(&s[i * rstride + j4]);
            fma2(acc[i], pack2(x.x, x.x), w0);
            fma2(acc[i], pack2(x.y, x.y), w1);
            fma2(acc[i], pack2(x.z, x.z), w2);
            fma2(acc[i], pack2(x.w, x.w), w3);
        }
    }

    #pragma unroll
    for (int i = 0; i < 8; i++)
        part[((w * 2 + rg) * 8 + i) * 16 + hp] = acc[i];
    __syncthreads();

    // 256 outputs (16 rows x 16 h-pairs); each thread finishes 2.
    u64 bias = __ldg(&biasp[tid & 15]);
    #pragma unroll
    for (int o = tid; o < 256; o += 128) {
        int row = o >> 4, h = o & 15;
        int ro = (row >> 3), ri = row & 7;
        u64 sum =      part[((0 * 2 + ro) * 8 + ri) * 16 + h];
        sum = add2(sum, part[((1 * 2 + ro) * 8 + ri) * 16 + h]);
        sum = add2(sum, part[((2 * 2 + ro) * 8 + ri) * 16 + h]);
        sum = add2(sum, part[((3 * 2 + ro) * 8 + ri) * 16 + h]);
        sum = add2(sum, bias);
        int grow = rowbase_cta + row;
        bool st = isQ || (((grow - B_ * Qn) & (Kn - 1)) < valid);
        if (st) dstbase[(size_t)grow * (Hn / 2) + h] = sum;
    }
}

// ---------------- attn phase helpers (generic / masked paths) ----------------

__device__ __forceinline__ void phaseA(const float* fkbuf, const float* fq_w,
                                       const float* wv, u64* pdst,
                                       int w, int lane, int kb, int valid,
                                       float& l_run) {
    float sacc[4] = {0.f, 0.f, 0.f, 0.f};
    const float4* fq4 = (const float4*)fq_w;
    const float4* wv4 = (const float4*)wv;
    const float4* fk4 = (const float4*)fkbuf;
    #pragma unroll
    for (int hb = 0; hb < 8; hb++) {
        float4 a = fq4[hb];
        float4 g = wv4[hb];
        #pragma unroll
        for (int i = 0; i < 4; i++) {
            float4 f = fk4[(lane + 32 * i) * 9 + hb];
            sacc[i] = fmaf(g.x, fast_tanh(a.x + f.x), sacc[i]);
            sacc[i] = fmaf(g.y, fast_tanh(a.y + f.y), sacc[i]);
            sacc[i] = fmaf(g.z, fast_tanh(a.z + f.z), sacc[i]);
            sacc[i] = fmaf(g.w, fast_tanh(a.w + f.w), sacc[i]);
        }
    }
    #pragma unroll
    for (int i = 0; i < 4; i++) {
        float p = (kb + lane + 32 * i < valid) ? __expf(sacc[i]) : 0.0f;
        l_run += p;
        pdst[(lane + 32 * i) * 10 + w] = pack2(p, p);
    }
}

__device__ __forceinline__ void phaseB(const u64* psrc, const float* vbatch,
                                       int kb, int valid, int w, int lane,
                                       u64 acc[TQ][2]) {
    const int kloc0 = (w >> 1) * 32;
    const int voff  = (w & 1) * 128;
    const u64* pbase = psrc + kloc0 * 10;
    const float* vb = vbatch + (size_t)(kb + kloc0) * VD + voff;
    int rem = valid - kb - kloc0;
    int kend = rem < 32 ? (rem < 0 ? 0 : rem) : 32;
    #pragma unroll 4
    for (int kk = 0; kk < kend; kk++) {
        ulonglong2 v = __ldg((const ulonglong2*)(vb + (size_t)kk * VD) + lane);
        const ulonglong2* prow2 = (const ulonglong2*)(pbase + kk * 10);
        #pragma unroll
        for (int qp = 0; qp < 4; qp++) {
            ulonglong2 pp = prow2[qp];
            fma2(acc[2 * qp][0],     v.x, pp.x);
            fma2(acc[2 * qp][1],     v.y, pp.x);
            fma2(acc[2 * qp + 1][0], v.x, pp.y);
            fma2(acc[2 * qp + 1][1], v.y, pp.y);
        }
    }
}

// ---------------- kernel 2: fused additive attention ----------------
// grid = (B, Q/TQ), block = 256 (8 warps), 3 CTAs/SM. (unchanged from R11)
// Software-pipelined: region c executes A(c+1) [MUFU-heavy] AND B(c) [LSU/FMA-
// heavy] between the same barriers; common full/full case hand-interleaved.
// No online softmax (|score| <= ||w_v||_1 since |tanh|<=1 -> exp safe in fp32).

__global__ __launch_bounds__(256, 3)
void attn_kernel(const float* __restrict__ values, const int* __restrict__ valid_lens,
                 const float* __restrict__ wvec, float* __restrict__ out) {
    __shared__ float fk_s[2][TK * 36];                   // [k][h], stride 36 floats
    __shared__ __align__(16) u64 pT2[2][TK * 10];        // [k][q] dup pair {p,p}, stride 10 u64
    __shared__ float fq_s[TQ * 32];
    __shared__ float wv_s[32];
    __shared__ float l_s[TQ];

    const int tid  = threadIdx.x;
    const int w    = tid >> 5;
    const int lane = tid & 31;
    const int b    = blockIdx.x;
    const int q0   = blockIdx.y * TQ;
    const int valid = valid_lens[b];

    fq_s[w * 32 + lane] = g_fq[((size_t)(b * Qn + q0 + w)) * Hn + lane];
    if (tid < 32) wv_s[tid] = wvec[tid];

    float l_run = 0.0f;
    u64 acc[TQ][2];
    #pragma unroll
    for (int q = 0; q < TQ; q++) { acc[q][0] = 0ull; acc[q][1] = 0ull; }

    const float* vbatch = values + (size_t)b * Kn * VD;
    const int nchunks = (valid + TK - 1) / TK;
    const int nfull   = valid / TK;

    // ---- Preload fk(0) into buffer 0 ----
    {
        const float4* src = (const float4*)(g_fk + ((size_t)(b * Kn)) * Hn);
        #pragma unroll
        for (int r = 0; r < 4; r++) {
            int idx = tid + 256 * r;
            unsigned int dst = (unsigned int)__cvta_generic_to_shared(
                &((float4*)fk_s[0])[(idx >> 3) * 9 + (idx & 7)]);
            cp_async16(dst, &src[idx]);
        }
        cp_async_commit();
        cp_async_wait0();
    }
    __syncthreads();

    // ---- Prologue: prefetch fk(1), compute A(0) ----
    if (nchunks > 1) {
        const float4* src = (const float4*)(g_fk + ((size_t)(b * Kn + TK)) * Hn);
        #pragma unroll
        for (int r = 0; r < 4; r++) {
            int idx = tid + 256 * r;
            unsigned int dst = (unsigned int)__cvta_generic_to_shared(
                &((float4*)fk_s[1])[(idx >> 3) * 9 + (idx & 7)]);
            cp_async16(dst, &src[idx]);
        }
        cp_async_commit();
    }
    phaseA(fk_s[0], fq_s + w * 32, wv_s, pT2[0], w, lane, 0, valid, l_run);
    if (nchunks > 1) cp_async_wait0();
    __syncthreads();

    // ---- Pipelined regions: region c = A(c+1) + B(c) ----
    for (int c = 0; c < nchunks; c++) {
        const int kb   = c * TK;
        const int bufB = c & 1;
        const int bufA = bufB ^ 1;

        if (c + 2 < nchunks) {     // prefetch fk(c+2) into fk_s[bufB] (fk(c) done)
            const float4* src = (const float4*)(g_fk + ((size_t)(b * Kn + kb + 2 * TK)) * Hn);
            #pragma unroll
            for (int r = 0; r < 4; r++) {
                int idx = tid + 256 * r;
                unsigned int dst = (unsigned int)__cvta_generic_to_shared(
                    &((float4*)fk_s[bufB])[(idx >> 3) * 9 + (idx & 7)]);
                cp_async16(dst, &src[idx]);
            }
            cp_async_commit();
        }

        if (c + 1 < nfull) {
            // ======== FAST PATH: A(c+1) full + B(c) full, hand-interleaved ========
            float sacc0 = 0.f, sacc1 = 0.f, sacc2 = 0.f, sacc3 = 0.f;
            const float4* fq4 = (const float4*)(fq_s + w * 32);
            const float4* wv4 = (const float4*)wv_s;
            const float4* fkA = (const float4*)fk_s[bufA];
            const int kloc0 = (w >> 1) * 32;
            const int voff  = (w & 1) * 128;
            const u64* pbase = pT2[bufB] + kloc0 * 10;
            const float* vb = vbatch + (size_t)(kb + kloc0) * VD + voff;

            #pragma unroll
            for (int s = 0; s < 8; s++) {
                float4 a = fq4[s];
                float4 g = wv4[s];
                float4 f0 = fkA[(lane)       * 9 + s];
                float4 f1 = fkA[(lane + 32)  * 9 + s];
                float4 f2 = fkA[(lane + 64)  * 9 + s];
                float4 f3 = fkA[(lane + 96)  * 9 + s];
                sacc0 = fmaf(g.x, fast_tanh(a.x + f0.x), sacc0);
                sacc0 = fmaf(g.y, fast_tanh(a.y + f0.y), sacc0);
                sacc0 = fmaf(g.z, fast_tanh(a.z + f0.z), sacc0);
                sacc0 = fmaf(g.w, fast_tanh(a.w + f0.w), sacc0);
                sacc1 = fmaf(g.x, fast_tanh(a.x + f1.x), sacc1);
                sacc1 = fmaf(g.y, fast_tanh(a.y + f1.y), sacc1);
                sacc1 = fmaf(g.z, fast_tanh(a.z + f1.z), sacc1);
                sacc1 = fmaf(g.w, fast_tanh(a.w + f1.w), sacc1);
                sacc2 = fmaf(g.x, fast_tanh(a.x + f2.x), sacc2);
                sacc2 = fmaf(g.y, fast_tanh(a.y + f2.y), sacc2);
                sacc2 = fmaf(g.z, fast_tanh(a.z + f2.z), sacc2);
                sacc2 = fmaf(g.w, fast_tanh(a.w + f2.w), sacc2);
                sacc3 = fmaf(g.x, fast_tanh(a.x + f3.x), sacc3);
                sacc3 = fmaf(g.y, fast_tanh(a.y + f3.y), sacc3);
                sacc3 = fmaf(g.z, fast_tanh(a.z + f3.z), sacc3);
                sacc3 = fmaf(g.w, fast_tanh(a.w + f3.w), sacc3);
                #pragma unroll
                for (int t = 0; t < 4; t++) {
                    int kk = 4 * s + t;
                    ulonglong2 v = __ldg((const ulonglong2*)(vb + (size_t)kk * VD) + lane);
                    const ulonglong2* prow2 = (const ulonglong2*)(pbase + kk * 10);
                    #pragma unroll
                    for (int qp = 0; qp < 4; qp++) {
                        ulonglong2 pp = prow2[qp];
                        fma2(acc[2 * qp][0],     v.x, pp.x);
                        fma2(acc[2 * qp][1],     v.y, pp.x);
                        fma2(acc[2 * qp + 1][0], v.x, pp.y);
                        fma2(acc[2 * qp + 1][1], v.y, pp.y);
                    }
                }
            }
            float p0 = __expf(sacc0), p1 = __expf(sacc1);
            float p2 = __expf(sacc2), p3 = __expf(sacc3);
            l_run += (p0 + p1) + (p2 + p3);
            pT2[bufA][(lane)       * 10 + w] = pack2(p0, p0);
            pT2[bufA][(lane + 32)  * 10 + w] = pack2(p1, p1);
            pT2[bufA][(lane + 64)  * 10 + w] = pack2(p2, p2);
            pT2[bufA][(lane + 96)  * 10 + w] = pack2(p3, p3);
        } else {
            // ======== GENERIC PATH (tail chunks) ========
            if (c + 1 < nchunks)
                phaseA(fk_s[bufA], fq_s + w * 32, wv_s, pT2[bufA],
                       w, lane, kb + TK, valid, l_run);
            phaseB(pT2[bufB], vbatch, kb, valid, w, lane, acc);
        }

        if (c + 2 < nchunks) cp_async_wait0();
        __syncthreads();
    }

    // -------- Epilogue: row-sums, then single-barrier cross-warp reduction --------
    float l = warp_sum(l_run);
    if (lane == 0) l_s[w] = l;

    float* bufp = fk_s[0];   // 32KB scratch inside fk_s
    #pragma unroll
    for (int q = 0; q < TQ; q++) {
        float f0, f1, f2, f3;
        unpack2(acc[q][0], f0, f1);
        unpack2(acc[q][1], f2, f3);
        float* d = bufp + (q * 8 + w) * 128 + lane * 4;
        d[0] = f0; d[1] = f1; d[2] = f2; d[3] = f3;
    }
    __syncthreads();

    {
        const int vhalf = tid >> 7;
        const int idx   = tid & 127;
        const size_t obase = ((size_t)(b * Qn + q0)) * VD + tid;
        #pragma unroll
        for (int q = 0; q < TQ; q++) {
            const float* s = bufp + q * 1024 + vhalf * 128 + idx;
            float tot = s[0] + s[256] + s[512] + s[768];
            out[obase + (size_t)q * VD] = tot * (1.0f / l_s[q]);
        }
    }
}

// ---------------- launch ----------------

extern "C" void kernel_launch(void* const* d_in, const int* in_sizes, int n_in,
                              void* d_out, int out_size) {
    const float* keys       = (const float*)d_in[0];
    const float* queries    = (const float*)d_in[1];
    const float* values     = (const float*)d_in[2];
    const int*   valid_lens = (const int*)d_in[3];
    const float* W_q        = (const float*)d_in[4];
    const float* b_q        = (const float*)d_in[5];
    const float* W_k        = (const float*)d_in[6];
    const float* b_k        = (const float*)d_in[7];
    const float* w_v        = (const float*)d_in[8];
    // b_v (d_in[9]) is softmax-invariant and intentionally unused.
    float* out = (float*)d_out;

    int total_rows = B_ * (Qn + Kn);            // 8192
    proj_kernel<<<total_rows / 16, 128>>>(queries, keys, W_q, b_q, W_k, b_k, valid_lens);

    dim3 grid(B_, Qn / TQ);
    attn_kernel<<<grid, 256>>>(values, valid_lens, w_v, out);
}